// round 7
// baseline (speedup 1.0000x reference)
#include <cuda_runtime.h>

#define INV_SCALE 0.35355339059327373f
#define SCENE_INV (1.0f / 1.5f)

// ---------------- scratch (static device globals; no allocation) ----------------
__device__ float g_vol32[28 * 32 * 32 * 32];              // 3.5 MB, channel-first
__device__ float g_vol64[28 * 64 * 64 * 64];              // 28 MB, channel-first
__device__ float g_vol128[128 * 128 * 128 * 32];          // 256 MB, channel-LAST (pad 28->32)

// ---------------- levels 0/1: channel-first IDWT ----------------
// One thread per input cell (c,i,j,k). Reads 8 subband values, 3D Hadamard
// butterfly, writes the 2x2x2 output block with float2 stores (coalesced along k).
template <int D, bool FIRST>
__global__ void idwt_cf_kernel(const float* __restrict__ ap_ext,
                               const float* __restrict__ det) {
    const int C = 28;
    const int total = C * D * D * D;
    int tid = blockIdx.x * blockDim.x + threadIdx.x;
    if (tid >= total) return;

    const float* src = FIRST ? ap_ext : g_vol32;
    float* dst = FIRST ? g_vol32 : g_vol64;

    int k = tid % D;
    int t = tid / D;
    int j = t % D; t /= D;
    int i = t % D;
    int c = t / D;

    const int sub = C * D * D * D;
    float a0 = src[tid];
    float a1 = det[0 * sub + tid];
    float a2 = det[1 * sub + tid];
    float a3 = det[2 * sub + tid];
    float a4 = det[3 * sub + tid];
    float a5 = det[4 * sub + tid];
    float a6 = det[5 * sub + tid];
    float a7 = det[6 * sub + tid];

    // stage u (first-letter / z)
    float u0 = a0 + a4, u4 = a0 - a4;
    float u1 = a1 + a5, u5 = a1 - a5;
    float u2 = a2 + a6, u6 = a2 - a6;
    float u3 = a3 + a7, u7 = a3 - a7;
    // stage v (y)
    float m0 = u0 + u2, m2 = u0 - u2;
    float m1 = u1 + u3, m3 = u1 - u3;
    float m4 = u4 + u6, m6 = u4 - u6;
    float m5 = u5 + u7, m7 = u5 - u7;
    // stage w (x)
    float o000 = (m0 + m1) * INV_SCALE;
    float o001 = (m0 - m1) * INV_SCALE;
    float o010 = (m2 + m3) * INV_SCALE;
    float o011 = (m2 - m3) * INV_SCALE;
    float o100 = (m4 + m5) * INV_SCALE;
    float o101 = (m4 - m5) * INV_SCALE;
    float o110 = (m6 + m7) * INV_SCALE;
    float o111 = (m6 - m7) * INV_SCALE;

    const int OD = 2 * D;
    size_t base = (((size_t)c * OD + 2 * i) * OD + (2 * j)) * OD + 2 * k;
    size_t rowY = OD;            // y+1
    size_t rowZ = (size_t)OD * OD;  // z+1
    *reinterpret_cast<float2*>(dst + base)               = make_float2(o000, o001);
    *reinterpret_cast<float2*>(dst + base + rowY)        = make_float2(o010, o011);
    *reinterpret_cast<float2*>(dst + base + rowZ)        = make_float2(o100, o101);
    *reinterpret_cast<float2*>(dst + base + rowZ + rowY) = make_float2(o110, o111);
}

// ---------------- level 2: IDWT with channel-last (transposed) output ----------------
// Block handles input tile (i, j, k0..k0+15) for ALL 28 channels.
// Output: 4 rows (2z x 2y) of 32 voxels x 32 floats each -> 4 x 4KB contiguous,
// fully coalesced stores (pad channels 28..31 written as 0).
__global__ void __launch_bounds__(256) idwt_cl_kernel(const float* __restrict__ det) {
    __shared__ float sub[8][16][29];   // [subband][k][channel], pad 29: conflict-free
    const int D = 64, C = 28;
    const int i = blockIdx.z;
    const int j = blockIdx.y;
    const int k0 = blockIdx.x * 16;
    const int t = threadIdx.x;
    const int subsz = C * D * D * D;

    // Stage loads: 8 subbands x 28 ch x 16 k = 3584 floats
    for (int l = t; l < 8 * 28 * 16; l += 256) {
        int s = l / 448;
        int rem = l - s * 448;
        int c = rem >> 4;
        int kk = rem & 15;
        int gidx = ((c * D + i) * D + j) * D + k0 + kk;
        float v = (s == 0) ? g_vol64[gidx] : det[(size_t)(s - 1) * subsz + gidx];
        sub[s][kk][c] = v;
    }
    __syncthreads();

    // 4096 output slots: slot = (row[2z x 2y] , x[0..31] , cslot[0..31])
#pragma unroll
    for (int iter = 0; iter < 16; ++iter) {
        int slot = t + iter * 256;
        int cs = slot & 31;
        int x = (slot >> 5) & 31;
        int rowid = slot >> 10;           // 0..3
        int p = rowid >> 1, q = rowid & 1;
        int k = x >> 1, r = x & 1;
        float val = 0.0f;
        if (cs < 28) {
            float a0 = sub[0][k][cs], a1 = sub[1][k][cs];
            float a2 = sub[2][k][cs], a3 = sub[3][k][cs];
            float a4 = sub[4][k][cs], a5 = sub[5][k][cs];
            float a6 = sub[6][k][cs], a7 = sub[7][k][cs];
            float sR = r ? -1.0f : 1.0f;
            float sQ = q ? -1.0f : 1.0f;
            float sP = p ? -1.0f : 1.0f;
            float b0 = a0 + sR * a1;
            float b1 = a2 + sR * a3;
            float b2 = a4 + sR * a5;
            float b3 = a6 + sR * a7;
            val = ((b0 + sQ * b1) + sP * (b2 + sQ * b3)) * INV_SCALE;
        }
        int z = 2 * i + p;
        int y = 2 * j + q;
        int gx = 2 * k0 + x;
        g_vol128[(((size_t)z * 128 + y) * 128 + gx) * 32 + cs] = val;
    }
}

// ---------------- trilinear query ----------------
// Thread per point; 8 corners x 7 float4 gathers from 128B voxel records;
// 28 register accumulators; 7 float4 coalesced output stores.
__global__ void __launch_bounds__(256) query_kernel(const float* __restrict__ xyz,
                                                    float* __restrict__ out, int N) {
    int n = blockIdx.x * blockDim.x + threadIdx.x;
    if (n >= N) return;

    float px = (xyz[3 * n + 0] * SCENE_INV + 1.0f) * 0.5f * 127.0f;
    float py = (xyz[3 * n + 1] * SCENE_INV + 1.0f) * 0.5f * 127.0f;
    float pz = (xyz[3 * n + 2] * SCENE_INV + 1.0f) * 0.5f * 127.0f;

    float flx = floorf(px), fly = floorf(py), flz = floorf(pz);
    int ix0 = (int)flx, iy0 = (int)fly, iz0 = (int)flz;
    float fx = px - flx, fy = py - fly, fz = pz - flz;

    // validity masks fold grid_sample zero-padding into the weights;
    // gathers use clamped indices (matches v*valid in the reference).
    float vx0 = (ix0 >= 0 && ix0 < 128) ? 1.0f : 0.0f;
    float vx1 = (ix0 + 1 >= 0 && ix0 + 1 < 128) ? 1.0f : 0.0f;
    float vy0 = (iy0 >= 0 && iy0 < 128) ? 1.0f : 0.0f;
    float vy1 = (iy0 + 1 >= 0 && iy0 + 1 < 128) ? 1.0f : 0.0f;
    float vz0 = (iz0 >= 0 && iz0 < 128) ? 1.0f : 0.0f;
    float vz1 = (iz0 + 1 >= 0 && iz0 + 1 < 128) ? 1.0f : 0.0f;

    int x0 = min(max(ix0, 0), 127), x1 = min(max(ix0 + 1, 0), 127);
    int y0 = min(max(iy0, 0), 127), y1 = min(max(iy0 + 1, 0), 127);
    int z0 = min(max(iz0, 0), 127), z1 = min(max(iz0 + 1, 0), 127);

    float wx0 = (1.0f - fx) * vx0, wx1 = fx * vx1;
    float wy0 = (1.0f - fy) * vy0, wy1 = fy * vy1;
    float wz0 = (1.0f - fz) * vz0, wz1 = fz * vz1;

    float acc[28];
#pragma unroll
    for (int c = 0; c < 28; ++c) acc[c] = 0.0f;

#pragma unroll
    for (int dz = 0; dz < 2; ++dz) {
        int zz = dz ? z1 : z0;
        float wz = dz ? wz1 : wz0;
#pragma unroll
        for (int dy = 0; dy < 2; ++dy) {
            int yy = dy ? y1 : y0;
            float wzy = wz * (dy ? wy1 : wy0);
#pragma unroll
            for (int dx = 0; dx < 2; ++dx) {
                int xx = dx ? x1 : x0;
                float w = wzy * (dx ? wx1 : wx0);
                const float4* p = reinterpret_cast<const float4*>(
                    g_vol128 + (((size_t)zz * 128 + yy) * 128 + xx) * 32);
#pragma unroll
                for (int u = 0; u < 7; ++u) {
                    float4 v = __ldg(p + u);
                    acc[4 * u + 0] += w * v.x;
                    acc[4 * u + 1] += w * v.y;
                    acc[4 * u + 2] += w * v.z;
                    acc[4 * u + 3] += w * v.w;
                }
            }
        }
    }

    float4* o = reinterpret_cast<float4*>(out + (size_t)n * 28);
#pragma unroll
    for (int u = 0; u < 7; ++u) {
        o[u] = make_float4(acc[4 * u + 0], acc[4 * u + 1], acc[4 * u + 2], acc[4 * u + 3]);
    }
}

extern "C" void kernel_launch(void* const* d_in, const int* in_sizes, int n_in,
                              void* d_out, int out_size) {
    const float* approx = (const float*)d_in[0];
    const float* det0 = (const float*)d_in[1];
    const float* det1 = (const float*)d_in[2];
    const float* det2 = (const float*)d_in[3];
    const float* xyz = (const float*)d_in[4];
    float* out = (float*)d_out;

    // Level 0: 16^3 -> 32^3 (channel-first)
    idwt_cf_kernel<16, true><<<(28 * 16 * 16 * 16 + 255) / 256, 256>>>(approx, det0);
    // Level 1: 32^3 -> 64^3 (channel-first)
    idwt_cf_kernel<32, false><<<(28 * 32 * 32 * 32 + 255) / 256, 256>>>(nullptr, det1);
    // Level 2: 64^3 -> 128^3 (channel-last, padded 32)
    dim3 g2(4, 64, 64);
    idwt_cl_kernel<<<g2, 256>>>(det2);
    // Query
    int N = in_sizes[4] / 3;
    query_kernel<<<(N + 255) / 256, 256>>>(xyz, out, N);
}

// round 10
// speedup vs baseline: 2.8387x; 2.8387x over previous
#include <cuda_runtime.h>
#include <cuda_fp16.h>

#define INV_SCALE 0.35355339059327373f
#define SCENE_INV (1.0f / 1.5f)

// ---------------- scratch (static device globals; no allocation) ----------------
__device__ float  g_vol32[28 * 32 * 32 * 32];               // 3.5 MB, channel-first fp32
__device__ float  g_vol64[28 * 64 * 64 * 64];               // 28 MB, channel-first fp32
__device__ __half g_vol128h[128 * 128 * 128 * 32];          // 128 MB, channel-LAST fp16 (pad 28->32)

// ---------------- levels 0/1: channel-first IDWT (fp32) ----------------
template <int D, bool FIRST>
__global__ void idwt_cf_kernel(const float* __restrict__ ap_ext,
                               const float* __restrict__ det) {
    const int C = 28;
    const int total = C * D * D * D;
    int tid = blockIdx.x * blockDim.x + threadIdx.x;
    if (tid >= total) return;

    const float* src = FIRST ? ap_ext : g_vol32;
    float* dst = FIRST ? g_vol32 : g_vol64;

    int k = tid % D;
    int t = tid / D;
    int j = t % D; t /= D;
    int i = t % D;
    int c = t / D;

    const int sub = C * D * D * D;
    float a0 = src[tid];
    float a1 = det[0 * sub + tid];
    float a2 = det[1 * sub + tid];
    float a3 = det[2 * sub + tid];
    float a4 = det[3 * sub + tid];
    float a5 = det[4 * sub + tid];
    float a6 = det[5 * sub + tid];
    float a7 = det[6 * sub + tid];

    float u0 = a0 + a4, u4 = a0 - a4;
    float u1 = a1 + a5, u5 = a1 - a5;
    float u2 = a2 + a6, u6 = a2 - a6;
    float u3 = a3 + a7, u7 = a3 - a7;
    float m0 = u0 + u2, m2 = u0 - u2;
    float m1 = u1 + u3, m3 = u1 - u3;
    float m4 = u4 + u6, m6 = u4 - u6;
    float m5 = u5 + u7, m7 = u5 - u7;
    float o000 = (m0 + m1) * INV_SCALE;
    float o001 = (m0 - m1) * INV_SCALE;
    float o010 = (m2 + m3) * INV_SCALE;
    float o011 = (m2 - m3) * INV_SCALE;
    float o100 = (m4 + m5) * INV_SCALE;
    float o101 = (m4 - m5) * INV_SCALE;
    float o110 = (m6 + m7) * INV_SCALE;
    float o111 = (m6 - m7) * INV_SCALE;

    const int OD = 2 * D;
    size_t base = (((size_t)c * OD + 2 * i) * OD + (2 * j)) * OD + 2 * k;
    size_t rowY = OD;
    size_t rowZ = (size_t)OD * OD;
    *reinterpret_cast<float2*>(dst + base)               = make_float2(o000, o001);
    *reinterpret_cast<float2*>(dst + base + rowY)        = make_float2(o010, o011);
    *reinterpret_cast<float2*>(dst + base + rowZ)        = make_float2(o100, o101);
    *reinterpret_cast<float2*>(dst + base + rowZ + rowY) = make_float2(o110, o111);
}

// ---------------- level 2: IDWT -> channel-last fp16 volume ----------------
// Block handles input tile (i, j, k0..k0+15) for ALL 28 channels.
// Each thread computes TWO adjacent channels and stores one half2.
// Warp store pattern: 16 lanes x half2 = one 64B voxel record; 2 records/warp
// -> 128B coalesced stores.
__global__ void __launch_bounds__(256) idwt_cl_kernel(const float* __restrict__ det) {
    __shared__ float sub[8][16][29];   // [subband][k][channel], pad 29: conflict-free
    const int D = 64, C = 28;
    const int i = blockIdx.z;
    const int j = blockIdx.y;
    const int k0 = blockIdx.x * 16;
    const int t = threadIdx.x;
    const int subsz = C * D * D * D;

    for (int l = t; l < 8 * 28 * 16; l += 256) {
        int s = l / 448;
        int rem = l - s * 448;
        int c = rem >> 4;
        int kk = rem & 15;
        int gidx = ((c * D + i) * D + j) * D + k0 + kk;
        float v = (s == 0) ? g_vol64[gidx] : det[(size_t)(s - 1) * subsz + gidx];
        sub[s][kk][c] = v;
    }
    __syncthreads();

    // 2048 half2 slots: slot = (row[2z x 2y], x[0..31], cpair[0..15])
    __half2* volh2 = reinterpret_cast<__half2*>(g_vol128h);
#pragma unroll
    for (int iter = 0; iter < 8; ++iter) {
        int slot = t + iter * 256;
        int cpair = slot & 15;
        int x = (slot >> 4) & 31;
        int rowid = slot >> 9;            // 0..3
        int p = rowid >> 1, q = rowid & 1;
        int k = x >> 1, r = x & 1;

        float sR = r ? -1.0f : 1.0f;
        float sQ = q ? -1.0f : 1.0f;
        float sP = p ? -1.0f : 1.0f;

        float v0 = 0.0f, v1 = 0.0f;
        int c0 = 2 * cpair;
        if (c0 < 28) {
            {
                float a0 = sub[0][k][c0], a1 = sub[1][k][c0];
                float a2 = sub[2][k][c0], a3 = sub[3][k][c0];
                float a4 = sub[4][k][c0], a5 = sub[5][k][c0];
                float a6 = sub[6][k][c0], a7 = sub[7][k][c0];
                float b0 = a0 + sR * a1;
                float b1 = a2 + sR * a3;
                float b2 = a4 + sR * a5;
                float b3 = a6 + sR * a7;
                v0 = ((b0 + sQ * b1) + sP * (b2 + sQ * b3)) * INV_SCALE;
            }
            {
                int c1 = c0 + 1;
                float a0 = sub[0][k][c1], a1 = sub[1][k][c1];
                float a2 = sub[2][k][c1], a3 = sub[3][k][c1];
                float a4 = sub[4][k][c1], a5 = sub[5][k][c1];
                float a6 = sub[6][k][c1], a7 = sub[7][k][c1];
                float b0 = a0 + sR * a1;
                float b1 = a2 + sR * a3;
                float b2 = a4 + sR * a5;
                float b3 = a6 + sR * a7;
                v1 = ((b0 + sQ * b1) + sP * (b2 + sQ * b3)) * INV_SCALE;
            }
        }

        int z = 2 * i + p;
        int y = 2 * j + q;
        int gx = 2 * k0 + x;
        size_t voxel = ((size_t)z * 128 + y) * 128 + gx;
        volh2[voxel * 16 + cpair] = __floats2half2_rn(v0, v1);
    }
}

// ---------------- trilinear query (fp16 volume, fp32 accumulation) ----------------
__device__ __forceinline__ void acc_pair(float& a0, float& a1, unsigned u, float w) {
    __half2 h = *reinterpret_cast<__half2*>(&u);
    float2 f = __half22float2(h);
    a0 = fmaf(w, f.x, a0);
    a1 = fmaf(w, f.y, a1);
}

__global__ void __launch_bounds__(256) query_kernel(const float* __restrict__ xyz,
                                                    float* __restrict__ out, int N) {
    int n = blockIdx.x * blockDim.x + threadIdx.x;
    if (n >= N) return;

    float px = (xyz[3 * n + 0] * SCENE_INV + 1.0f) * 0.5f * 127.0f;
    float py = (xyz[3 * n + 1] * SCENE_INV + 1.0f) * 0.5f * 127.0f;
    float pz = (xyz[3 * n + 2] * SCENE_INV + 1.0f) * 0.5f * 127.0f;

    float flx = floorf(px), fly = floorf(py), flz = floorf(pz);
    int ix0 = (int)flx, iy0 = (int)fly, iz0 = (int)flz;
    float fx = px - flx, fy = py - fly, fz = pz - flz;

    float vx0 = (ix0 >= 0 && ix0 < 128) ? 1.0f : 0.0f;
    float vx1 = (ix0 + 1 >= 0 && ix0 + 1 < 128) ? 1.0f : 0.0f;
    float vy0 = (iy0 >= 0 && iy0 < 128) ? 1.0f : 0.0f;
    float vy1 = (iy0 + 1 >= 0 && iy0 + 1 < 128) ? 1.0f : 0.0f;
    float vz0 = (iz0 >= 0 && iz0 < 128) ? 1.0f : 0.0f;
    float vz1 = (iz0 + 1 >= 0 && iz0 + 1 < 128) ? 1.0f : 0.0f;

    int x0 = min(max(ix0, 0), 127), x1 = min(max(ix0 + 1, 0), 127);
    int y0 = min(max(iy0, 0), 127), y1 = min(max(iy0 + 1, 0), 127);
    int z0 = min(max(iz0, 0), 127), z1 = min(max(iz0 + 1, 0), 127);

    float wx0 = (1.0f - fx) * vx0, wx1 = fx * vx1;
    float wy0 = (1.0f - fy) * vy0, wy1 = fy * vy1;
    float wz0 = (1.0f - fz) * vz0, wz1 = fz * vz1;

    float acc[28];
#pragma unroll
    for (int c = 0; c < 28; ++c) acc[c] = 0.0f;

#pragma unroll
    for (int dz = 0; dz < 2; ++dz) {
        int zz = dz ? z1 : z0;
        float wz = dz ? wz1 : wz0;
#pragma unroll
        for (int dy = 0; dy < 2; ++dy) {
            int yy = dy ? y1 : y0;
            float wzy = wz * (dy ? wy1 : wy0);
#pragma unroll
            for (int dx = 0; dx < 2; ++dx) {
                int xx = dx ? x1 : x0;
                float w = wzy * (dx ? wx1 : wx0);
                const __half* rec = g_vol128h + (((size_t)zz * 128 + yy) * 128 + xx) * 32;
                const uint4* p4 = reinterpret_cast<const uint4*>(rec);
                uint4 v0 = __ldg(p4 + 0);   // ch 0..7
                uint4 v1 = __ldg(p4 + 1);   // ch 8..15
                uint4 v2 = __ldg(p4 + 2);   // ch 16..23
                uint2 v3 = __ldg(reinterpret_cast<const uint2*>(rec + 24)); // ch 24..27
                acc_pair(acc[0],  acc[1],  v0.x, w);
                acc_pair(acc[2],  acc[3],  v0.y, w);
                acc_pair(acc[4],  acc[5],  v0.z, w);
                acc_pair(acc[6],  acc[7],  v0.w, w);
                acc_pair(acc[8],  acc[9],  v1.x, w);
                acc_pair(acc[10], acc[11], v1.y, w);
                acc_pair(acc[12], acc[13], v1.z, w);
                acc_pair(acc[14], acc[15], v1.w, w);
                acc_pair(acc[16], acc[17], v2.x, w);
                acc_pair(acc[18], acc[19], v2.y, w);
                acc_pair(acc[20], acc[21], v2.z, w);
                acc_pair(acc[22], acc[23], v2.w, w);
                acc_pair(acc[24], acc[25], v3.x, w);
                acc_pair(acc[26], acc[27], v3.y, w);
            }
        }
    }

    float4* o = reinterpret_cast<float4*>(out + (size_t)n * 28);
#pragma unroll
    for (int u = 0; u < 7; ++u) {
        o[u] = make_float4(acc[4 * u + 0], acc[4 * u + 1], acc[4 * u + 2], acc[4 * u + 3]);
    }
}

extern "C" void kernel_launch(void* const* d_in, const int* in_sizes, int n_in,
                              void* d_out, int out_size) {
    const float* approx = (const float*)d_in[0];
    const float* det0 = (const float*)d_in[1];
    const float* det1 = (const float*)d_in[2];
    const float* det2 = (const float*)d_in[3];
    const float* xyz = (const float*)d_in[4];
    float* out = (float*)d_out;

    idwt_cf_kernel<16, true><<<(28 * 16 * 16 * 16 + 255) / 256, 256>>>(approx, det0);
    idwt_cf_kernel<32, false><<<(28 * 32 * 32 * 32 + 255) / 256, 256>>>(nullptr, det1);
    dim3 g2(4, 64, 64);
    idwt_cl_kernel<<<g2, 256>>>(det2);
    int N = in_sizes[4] / 3;
    query_kernel<<<(N + 255) / 256, 256>>>(xyz, out, N);
}

// round 12
// speedup vs baseline: 3.4753x; 1.2243x over previous
#include <cuda_runtime.h>
#include <cuda_fp16.h>

#define INV_SCALE 0.35355339059327373f
#define SCENE_INV (1.0f / 1.5f)

// ---------------- scratch (static device globals; no allocation) ----------------
__device__ float  g_vol32[28 * 32 * 32 * 32];               // 3.5 MB, channel-first fp32
__device__ float  g_vol64[28 * 64 * 64 * 64];               // 28 MB, channel-first fp32
__device__ __half g_vol128h[128 * 128 * 128 * 32];          // 128 MB, channel-LAST fp16 (pad 28->32)

// ---------------- levels 0/1: channel-first IDWT (fp32) ----------------
template <int D, bool FIRST>
__global__ void idwt_cf_kernel(const float* __restrict__ ap_ext,
                               const float* __restrict__ det) {
    const int C = 28;
    const int total = C * D * D * D;
    int tid = blockIdx.x * blockDim.x + threadIdx.x;
    if (tid >= total) return;

    const float* src = FIRST ? ap_ext : g_vol32;
    float* dst = FIRST ? g_vol32 : g_vol64;

    int k = tid % D;
    int t = tid / D;
    int j = t % D; t /= D;
    int i = t % D;
    int c = t / D;

    const int sub = C * D * D * D;
    float a0 = src[tid];
    float a1 = det[0 * sub + tid];
    float a2 = det[1 * sub + tid];
    float a3 = det[2 * sub + tid];
    float a4 = det[3 * sub + tid];
    float a5 = det[4 * sub + tid];
    float a6 = det[5 * sub + tid];
    float a7 = det[6 * sub + tid];

    float u0 = a0 + a4, u4 = a0 - a4;
    float u1 = a1 + a5, u5 = a1 - a5;
    float u2 = a2 + a6, u6 = a2 - a6;
    float u3 = a3 + a7, u7 = a3 - a7;
    float m0 = u0 + u2, m2 = u0 - u2;
    float m1 = u1 + u3, m3 = u1 - u3;
    float m4 = u4 + u6, m6 = u4 - u6;
    float m5 = u5 + u7, m7 = u5 - u7;
    float o000 = (m0 + m1) * INV_SCALE;
    float o001 = (m0 - m1) * INV_SCALE;
    float o010 = (m2 + m3) * INV_SCALE;
    float o011 = (m2 - m3) * INV_SCALE;
    float o100 = (m4 + m5) * INV_SCALE;
    float o101 = (m4 - m5) * INV_SCALE;
    float o110 = (m6 + m7) * INV_SCALE;
    float o111 = (m6 - m7) * INV_SCALE;

    const int OD = 2 * D;
    size_t base = (((size_t)c * OD + 2 * i) * OD + (2 * j)) * OD + 2 * k;
    size_t rowY = OD;
    size_t rowZ = (size_t)OD * OD;
    *reinterpret_cast<float2*>(dst + base)               = make_float2(o000, o001);
    *reinterpret_cast<float2*>(dst + base + rowY)        = make_float2(o010, o011);
    *reinterpret_cast<float2*>(dst + base + rowZ)        = make_float2(o100, o101);
    *reinterpret_cast<float2*>(dst + base + rowZ + rowY) = make_float2(o110, o111);
}

// ---------------- level 2: IDWT -> channel-last fp16 volume ----------------
// Block = input tile (i, j, k0..k0+15), all 28 channels.
// NEW: each thread owns one (k, channel-pair) and computes the FULL 2x2x2
// butterfly: 16 LDS -> 16 outputs (8x less smem traffic than slot-per-thread).
// Warp store per (p,q,r): lanes 0-15 = one 64B voxel record, lanes 16-31 the
// record at x+2 -> two 64B fully-written chunks per store instruction.
__global__ void __launch_bounds__(256) idwt_cl_kernel(const float* __restrict__ det) {
    __shared__ float sub[8][16][29];   // [subband][k][channel], pad 29: conflict-free
    const int D = 64;
    const int i = blockIdx.z;
    const int j = blockIdx.y;
    const int k0 = blockIdx.x * 16;
    const int t = threadIdx.x;
    const int subsz = 28 * D * D * D;

    for (int l = t; l < 8 * 28 * 16; l += 256) {
        int s = l / 448;
        int rem = l - s * 448;
        int c = rem >> 4;
        int kk = rem & 15;
        int gidx = ((c * D + i) * D + j) * D + k0 + kk;
        float v = (s == 0) ? g_vol64[gidx] : det[(size_t)(s - 1) * subsz + gidx];
        sub[s][kk][c] = v;
    }
    __syncthreads();

    const int k = t >> 4;       // 0..15
    const int cpair = t & 15;   // 0..15
    const int c0 = 2 * cpair;

    float oc[2][8];             // [channel][p*4+q*2+r]
#pragma unroll
    for (int cc = 0; cc < 2; ++cc) {
        int c = c0 + cc;
        float a0 = 0.f, a1 = 0.f, a2 = 0.f, a3 = 0.f;
        float a4 = 0.f, a5 = 0.f, a6 = 0.f, a7 = 0.f;
        if (c < 28) {
            a0 = sub[0][k][c]; a1 = sub[1][k][c];
            a2 = sub[2][k][c]; a3 = sub[3][k][c];
            a4 = sub[4][k][c]; a5 = sub[5][k][c];
            a6 = sub[6][k][c]; a7 = sub[7][k][c];
        }
        // w-stage (pairs with r)
        float w0p = a0 + a1, w0m = a0 - a1;
        float w1p = a2 + a3, w1m = a2 - a3;
        float w2p = a4 + a5, w2m = a4 - a5;
        float w3p = a6 + a7, w3m = a6 - a7;
        // v-stage (q), u-stage (p)
        float s01 = w0p + w1p, d01 = w0p - w1p;
        float s23 = w2p + w3p, d23 = w2p - w3p;
        float s01m = w0m + w1m, d01m = w0m - w1m;
        float s23m = w2m + w3m, d23m = w2m - w3m;
        oc[cc][0] = (s01 + s23) * INV_SCALE;    // p0 q0 r0
        oc[cc][1] = (s01m + s23m) * INV_SCALE;  // p0 q0 r1
        oc[cc][2] = (d01 + d23) * INV_SCALE;    // p0 q1 r0
        oc[cc][3] = (d01m + d23m) * INV_SCALE;  // p0 q1 r1
        oc[cc][4] = (s01 - s23) * INV_SCALE;    // p1 q0 r0
        oc[cc][5] = (s01m - s23m) * INV_SCALE;  // p1 q0 r1
        oc[cc][6] = (d01 - d23) * INV_SCALE;    // p1 q1 r0
        oc[cc][7] = (d01m - d23m) * INV_SCALE;  // p1 q1 r1
    }

    __half2* volh2 = reinterpret_cast<__half2*>(g_vol128h);
    const int z0 = 2 * i, y0 = 2 * j, x0 = 2 * (k0 + k);
#pragma unroll
    for (int m = 0; m < 8; ++m) {
        int p = m >> 2, q = (m >> 1) & 1, r = m & 1;
        size_t voxel = ((size_t)(z0 + p) * 128 + (y0 + q)) * 128 + (x0 + r);
        volh2[voxel * 16 + cpair] = __floats2half2_rn(oc[0][m], oc[1][m]);
    }
}

// ---------------- trilinear query: 2 threads per point ----------------
// Thread pair (h=0,1) splits the 64B voxel record: each half does 8 corners
// x 2 uint4 loads + 14 fp32 accumulators. Results staged in smem so the
// final global stores are fully coalesced float4s.
__device__ __forceinline__ void acc_pair(float& a0, float& a1, unsigned u, float w) {
    __half2 hh = *reinterpret_cast<__half2*>(&u);
    float2 f = __half22float2(hh);
    a0 = fmaf(w, f.x, a0);
    a1 = fmaf(w, f.y, a1);
}

__global__ void __launch_bounds__(256) query_kernel(const float* __restrict__ xyz,
                                                    float* __restrict__ out, int N) {
    __shared__ float sOut[128 * 28];
    const int t = threadIdx.x;
    const int nl = t >> 1;           // local point 0..127
    const int h = t & 1;             // record half
    const int nBase = blockIdx.x * 128;
    const int n = nBase + nl;

    float acc[14];
#pragma unroll
    for (int c = 0; c < 14; ++c) acc[c] = 0.0f;

    if (n < N) {
        float px = (__ldg(xyz + 3 * n + 0) * SCENE_INV + 1.0f) * 0.5f * 127.0f;
        float py = (__ldg(xyz + 3 * n + 1) * SCENE_INV + 1.0f) * 0.5f * 127.0f;
        float pz = (__ldg(xyz + 3 * n + 2) * SCENE_INV + 1.0f) * 0.5f * 127.0f;

        float flx = floorf(px), fly = floorf(py), flz = floorf(pz);
        int ix0 = (int)flx, iy0 = (int)fly, iz0 = (int)flz;
        float fx = px - flx, fy = py - fly, fz = pz - flz;

        float vx0 = (ix0 >= 0 && ix0 < 128) ? 1.0f : 0.0f;
        float vx1 = (ix0 + 1 >= 0 && ix0 + 1 < 128) ? 1.0f : 0.0f;
        float vy0 = (iy0 >= 0 && iy0 < 128) ? 1.0f : 0.0f;
        float vy1 = (iy0 + 1 >= 0 && iy0 + 1 < 128) ? 1.0f : 0.0f;
        float vz0 = (iz0 >= 0 && iz0 < 128) ? 1.0f : 0.0f;
        float vz1 = (iz0 + 1 >= 0 && iz0 + 1 < 128) ? 1.0f : 0.0f;

        int x0 = min(max(ix0, 0), 127), x1 = min(max(ix0 + 1, 0), 127);
        int y0 = min(max(iy0, 0), 127), y1 = min(max(iy0 + 1, 0), 127);
        int z0 = min(max(iz0, 0), 127), z1 = min(max(iz0 + 1, 0), 127);

        float wx0 = (1.0f - fx) * vx0, wx1 = fx * vx1;
        float wy0 = (1.0f - fy) * vy0, wy1 = fy * vy1;
        float wz0 = (1.0f - fz) * vz0, wz1 = fz * vz1;

        const __half* volBase = g_vol128h + h * 16;   // this thread's 32B half

#pragma unroll
        for (int dz = 0; dz < 2; ++dz) {
            int zz = dz ? z1 : z0;
            float wz = dz ? wz1 : wz0;
#pragma unroll
            for (int dy = 0; dy < 2; ++dy) {
                int yy = dy ? y1 : y0;
                float wzy = wz * (dy ? wy1 : wy0);
#pragma unroll
                for (int dx = 0; dx < 2; ++dx) {
                    int xx = dx ? x1 : x0;
                    float w = wzy * (dx ? wx1 : wx0);
                    const uint4* p4 = reinterpret_cast<const uint4*>(
                        volBase + (((size_t)zz * 128 + yy) * 128 + xx) * 32);
                    uint4 va = __ldg(p4 + 0);    // ch 14h+0 .. 14h+7
                    uint4 vb = __ldg(p4 + 1);    // ch 14h+8 .. 14h+13 (+2 pad for h=1)
                    acc_pair(acc[0],  acc[1],  va.x, w);
                    acc_pair(acc[2],  acc[3],  va.y, w);
                    acc_pair(acc[4],  acc[5],  va.z, w);
                    acc_pair(acc[6],  acc[7],  va.w, w);
                    acc_pair(acc[8],  acc[9],  vb.x, w);
                    acc_pair(acc[10], acc[11], vb.y, w);
                    acc_pair(acc[12], acc[13], vb.z, w);
                    // vb.w = pad channels for h=1; for h=0 it's ch 14,15 — handled below
                    if (h == 0) {
                        // h=0 half covers channels 0..15 in the record, but we only
                        // own 0..13; ch 14,15 belong to h=1's logical half? No:
                        // record layout is ch 0..27 + pad. h=0 loads ch 0..15,
                        // h=1 loads ch 16..31. So h=0 owns ch 0..13? It owns 0..15.
                    }
                }
            }
        }
    }

    // NOTE on channel split: h=0 half of the record = channels 0..15,
    // h=1 half = channels 16..31 (27 valid + pad). acc[] above holds 14
    // accumulated pairs-worth = 16 channels in 8 half2... but acc has only 14
    // slots. Corrected below by accumulating vb.w too for h=0 and masking pad
    // for h=1 — see acc16 version.
    // (This comment block is informational; the code below uses acc16.)

    // write 14 floats per thread to smem staging:
    // h=0 -> channels 0..13?  We must write channels 0..15 / 16..27.
    // Simplest correct mapping: h=0 owns ch 0..13 is WRONG for the load split.
    // Therefore: h=0 stages ch 0..15 (16 floats), h=1 stages ch 16..27 (12).
    // Handled by acc16 below.
    (void)sOut;
    // --- unreachable placeholder; real implementation in query_kernel2 ---
}

// ---------------- corrected query (h=0: ch 0..15, h=1: ch 16..27) ----------------
__global__ void __launch_bounds__(256) query_kernel2(const float* __restrict__ xyz,
                                                     float* __restrict__ out, int N) {
    __shared__ float sOut[128 * 28];
    const int t = threadIdx.x;
    const int nl = t >> 1;
    const int h = t & 1;
    const int nBase = blockIdx.x * 128;
    const int n = nBase + nl;

    float acc[16];
#pragma unroll
    for (int c = 0; c < 16; ++c) acc[c] = 0.0f;

    if (n < N) {
        float px = (__ldg(xyz + 3 * n + 0) * SCENE_INV + 1.0f) * 0.5f * 127.0f;
        float py = (__ldg(xyz + 3 * n + 1) * SCENE_INV + 1.0f) * 0.5f * 127.0f;
        float pz = (__ldg(xyz + 3 * n + 2) * SCENE_INV + 1.0f) * 0.5f * 127.0f;

        float flx = floorf(px), fly = floorf(py), flz = floorf(pz);
        int ix0 = (int)flx, iy0 = (int)fly, iz0 = (int)flz;
        float fx = px - flx, fy = py - fly, fz = pz - flz;

        float vx0 = (ix0 >= 0 && ix0 < 128) ? 1.0f : 0.0f;
        float vx1 = (ix0 + 1 >= 0 && ix0 + 1 < 128) ? 1.0f : 0.0f;
        float vy0 = (iy0 >= 0 && iy0 < 128) ? 1.0f : 0.0f;
        float vy1 = (iy0 + 1 >= 0 && iy0 + 1 < 128) ? 1.0f : 0.0f;
        float vz0 = (iz0 >= 0 && iz0 < 128) ? 1.0f : 0.0f;
        float vz1 = (iz0 + 1 >= 0 && iz0 + 1 < 128) ? 1.0f : 0.0f;

        int x0 = min(max(ix0, 0), 127), x1 = min(max(ix0 + 1, 0), 127);
        int y0 = min(max(iy0, 0), 127), y1 = min(max(iy0 + 1, 0), 127);
        int z0 = min(max(iz0, 0), 127), z1 = min(max(iz0 + 1, 0), 127);

        float wx0 = (1.0f - fx) * vx0, wx1 = fx * vx1;
        float wy0 = (1.0f - fy) * vy0, wy1 = fy * vy1;
        float wz0 = (1.0f - fz) * vz0, wz1 = fz * vz1;

        const __half* volBase = g_vol128h + h * 16;   // h=0: ch0..15, h=1: ch16..31

#pragma unroll
        for (int dz = 0; dz < 2; ++dz) {
            int zz = dz ? z1 : z0;
            float wz = dz ? wz1 : wz0;
#pragma unroll
            for (int dy = 0; dy < 2; ++dy) {
                int yy = dy ? y1 : y0;
                float wzy = wz * (dy ? wy1 : wy0);
#pragma unroll
                for (int dx = 0; dx < 2; ++dx) {
                    int xx = dx ? x1 : x0;
                    float w = wzy * (dx ? wx1 : wx0);
                    const uint4* p4 = reinterpret_cast<const uint4*>(
                        volBase + (((size_t)zz * 128 + yy) * 128 + xx) * 32);
                    uint4 va = __ldg(p4 + 0);
                    uint4 vb = __ldg(p4 + 1);
                    acc_pair(acc[0],  acc[1],  va.x, w);
                    acc_pair(acc[2],  acc[3],  va.y, w);
                    acc_pair(acc[4],  acc[5],  va.z, w);
                    acc_pair(acc[6],  acc[7],  va.w, w);
                    acc_pair(acc[8],  acc[9],  vb.x, w);
                    acc_pair(acc[10], acc[11], vb.y, w);
                    acc_pair(acc[12], acc[13], vb.z, w);
                    acc_pair(acc[14], acc[15], vb.w, w);   // pad for h=1 (discarded)
                }
            }
        }
    }

    // Stage to smem: h=0 writes ch 0..15, h=1 writes ch 16..27 (12 floats).
    float* row = sOut + nl * 28;
    if (h == 0) {
#pragma unroll
        for (int u = 0; u < 8; ++u)
            *reinterpret_cast<float2*>(row + 2 * u) = make_float2(acc[2 * u], acc[2 * u + 1]);
    } else {
#pragma unroll
        for (int u = 0; u < 6; ++u)
            *reinterpret_cast<float2*>(row + 16 + 2 * u) = make_float2(acc[2 * u], acc[2 * u + 1]);
    }
    __syncthreads();

    // Coalesced block store of the valid region.
    int validPts = min(128, N - nBase);
    int totalF4 = validPts * 7;                 // 28 floats = 7 float4 per point
    float4* o4 = reinterpret_cast<float4*>(out + (size_t)nBase * 28);
    const float4* s4 = reinterpret_cast<const float4*>(sOut);
    for (int idx = t; idx < totalF4; idx += 256)
        o4[idx] = s4[idx];
}

extern "C" void kernel_launch(void* const* d_in, const int* in_sizes, int n_in,
                              void* d_out, int out_size) {
    const float* approx = (const float*)d_in[0];
    const float* det0 = (const float*)d_in[1];
    const float* det1 = (const float*)d_in[2];
    const float* det2 = (const float*)d_in[3];
    const float* xyz = (const float*)d_in[4];
    float* out = (float*)d_out;

    idwt_cf_kernel<16, true><<<(28 * 16 * 16 * 16 + 255) / 256, 256>>>(approx, det0);
    idwt_cf_kernel<32, false><<<(28 * 32 * 32 * 32 + 255) / 256, 256>>>(nullptr, det1);
    dim3 g2(4, 64, 64);
    idwt_cl_kernel<<<g2, 256>>>(det2);
    int N = in_sizes[4] / 3;
    int blocks = (N + 127) / 128;
    query_kernel2<<<blocks, 256>>>(xyz, out, N);
}